// round 12
// baseline (speedup 1.0000x reference)
#include <cuda_runtime.h>
#include <cuda_bf16.h>

// SE block: B=32, H=W=56 (HW=3136), C=256, R=16
#define HW      3136
#define CCH     256
#define NB      32
#define ROWS    32               // rows per unit
#define UPB     98               // units per batch (3136/32)
#define HB      16               // batches per half
#define HUNITS  (HB * UPB)       // 1568 units per half
#define NBLK    592              // 148 SMs * 4, co-resident (validated)

// Scratch (__device__ globals; zero-init at load; self-resetting)
__device__ float g_partial[NB * UPB * CCH];  // [b][s][c]
__device__ float g_gate[NB * CCH];
__device__ unsigned g_done[NB];              // per-batch pooled-unit counters
__device__ unsigned g_count = 0;             // barrier arrivals
__device__ unsigned g_gen   = 0;             // barrier generation

__device__ __forceinline__ void grid_barrier() {
    __syncthreads();
    if (threadIdx.x == 0) {
        unsigned gen = *((volatile unsigned*)&g_gen);
        __threadfence();
        if (atomicAdd(&g_count, 1u) == NBLK - 1) {
            g_count = 0;
            __threadfence();
            atomicAdd(&g_gen, 1u);
        } else {
            while (*((volatile unsigned*)&g_gen) == gen) { }
        }
        __threadfence();
    }
    __syncthreads();
}

struct SMem {
    float4 red[256];        // pool reduction / MLP partials
    float  s_s[CCH];
    float  s_h[16];
    float  s_w1[CCH * 16];
    int    flag;
};

// Pool one 32-row unit (b, s); the block completing batch b runs its MLP inline.
__device__ __forceinline__ void do_pool(int b, int s, int t, int c4, int ho,
                                        const float4* __restrict__ x4,
                                        const float* __restrict__ w1,
                                        const float* __restrict__ b1,
                                        const float* __restrict__ w2,
                                        const float* __restrict__ b2,
                                        SMem* sm) {
    const size_t base = ((size_t)b * HW + (size_t)s * ROWS + ho) * (CCH / 4) + c4;
    float4 acc = make_float4(0.f, 0.f, 0.f, 0.f);
#pragma unroll
    for (int k = 0; k < 8; k++) {
        float4 v = x4[base + (size_t)k * 4 * (CCH / 4)];
        acc.x += v.x; acc.y += v.y; acc.z += v.z; acc.w += v.w;
    }
    sm->red[t] = acc;
    __syncthreads();
    if (t < 64) {
        float4 a = sm->red[t], e = sm->red[t + 64], f = sm->red[t + 128], h = sm->red[t + 192];
        float4 r = make_float4(a.x + e.x + f.x + h.x,
                               a.y + e.y + f.y + h.y,
                               a.z + e.z + f.z + h.z,
                               a.w + e.w + f.w + h.w);
        reinterpret_cast<float4*>(g_partial)[((size_t)b * UPB + s) * (CCH / 4) + t] = r;
    }
    __threadfence();
    __syncthreads();
    if (t == 0) {
        unsigned old = atomicAdd(&g_done[b], 1u);
        sm->flag = (old == UPB - 1);
    }
    __syncthreads();
    if (!sm->flag) return;

    // ---- inline MLP for batch b (fixed-order, deterministic) ----
    if (t == 0) g_done[b] = 0;   // reset for next graph replay (sole reader)
#pragma unroll
    for (int i = t; i < CCH * 16; i += 256) sm->s_w1[i] = w1[i];

    float accm = 0.f;
#pragma unroll 7
    for (int ss = 0; ss < UPB; ss++)
        accm += __ldcg(&g_partial[((size_t)b * UPB + ss) * CCH + t]);
    sm->s_s[t] = accm * (1.0f / (float)HW);
    __syncthreads();

    {   // dense1: t = grp*16 + cout
        const int cout = t & 15;
        const int grp  = t >> 4;
        float p = 0.f;
#pragma unroll
        for (int k = grp * 16; k < grp * 16 + 16; k++)
            p = fmaf(sm->s_s[k], sm->s_w1[k * 16 + cout], p);
        reinterpret_cast<float*>(sm->red)[t] = p;
    }
    __syncthreads();
    if (t < 16) {
        float h = b1[t];
#pragma unroll
        for (int j = 0; j < 16; j++)
            h += reinterpret_cast<float*>(sm->red)[j * 16 + t];
        sm->s_h[t] = fmaxf(h, 0.f);
    }
    __syncthreads();

    float g = b2[t];
#pragma unroll
    for (int j = 0; j < 16; j++)
        g = fmaf(sm->s_h[j], w2[j * CCH + t], g);
    g_gate[b * CCH + t] = 1.f / (1.f + __expf(-g));
    __syncthreads();
}

__device__ __forceinline__ void do_scale(int b, int s, int t, int c4, int ho,
                                         const float4* __restrict__ x4,
                                         float4* __restrict__ o4) {
    const float4 g = reinterpret_cast<const float4*>(g_gate)[b * (CCH / 4) + c4];
    const size_t base = ((size_t)b * HW + (size_t)s * ROWS + ho) * (CCH / 4) + c4;
#pragma unroll
    for (int k = 0; k < 8; k++) {
        const size_t idx = base + (size_t)k * 4 * (CCH / 4);
        float4 v = x4[idx];            // L2 hit (pooled 1 stage earlier)
        v.x *= g.x; v.y *= g.y; v.z *= g.z; v.w *= g.w;
        o4[idx] = v;                   // write-back: lazy DRAM drain (R11 win)
    }
}

__global__ void __launch_bounds__(256, 4)
k_se(const float* __restrict__ x,
     const float* __restrict__ w1,
     const float* __restrict__ b1,
     const float* __restrict__ w2,
     const float* __restrict__ b2,
     float* __restrict__ out) {
    const int bid = blockIdx.x;
    const int t   = threadIdx.x;
    const int c4  = t & 63;
    const int ho  = t >> 6;

    const float4* x4 = reinterpret_cast<const float4*>(x);
    float4*       o4 = reinterpret_cast<float4*>(out);

    __shared__ SMem sm;

    // ---- S0: pool half A (batches 0..15), inline MLPs ----
    for (int u = bid; u < HUNITS; u += NBLK) {
        const int b = u / UPB, s = u - b * UPB;
        do_pool(b, s, t, c4, ho, x4, w1, b1, w2, b2, &sm);
    }

    grid_barrier();   // gates for A ready; x(A) resident in L2

    // ---- S1: pool half B + scale half A, interleaved (duplex DRAM) ----
    for (int u = bid; u < HUNITS; u += NBLK) {
        const int b = u / UPB, s = u - b * UPB;
        do_pool(b + HB, s, t, c4, ho, x4, w1, b1, w2, b2, &sm);
        do_scale(b, s, t, c4, ho, x4, o4);
    }

    grid_barrier();   // gates for B ready; x(B) resident in L2

    // ---- S2: scale half B ----
    for (int u = bid; u < HUNITS; u += NBLK) {
        const int b = u / UPB, s = u - b * UPB;
        do_scale(b + HB, s, t, c4, ho, x4, o4);
    }
}

extern "C" void kernel_launch(void* const* d_in, const int* in_sizes, int n_in,
                              void* d_out, int out_size) {
    const float* x  = (const float*)d_in[0];
    const float* w1 = (const float*)d_in[1];
    const float* b1 = (const float*)d_in[2];
    const float* w2 = (const float*)d_in[3];
    const float* b2 = (const float*)d_in[4];
    float* out = (float*)d_out;

    k_se<<<NBLK, 256>>>(x, w1, b1, w2, b2, out);
}

// round 13
// speedup vs baseline: 1.3499x; 1.3499x over previous
#include <cuda_runtime.h>
#include <cuda_bf16.h>

// SE block: B=32, H=W=56 (HW=3136), C=256, R=16
#define HW      3136
#define CCH     256
#define NB      32
#define NS      49               // 64-row units per batch
#define CHUNK   64
#define HB      16               // batches per half
#define HUNITS  (HB * NS)        // 784 units per half
#define NBLK    592              // co-resident at 4/SM (validated)
#define HALFB   296              // blocks per role in stage B

// Scratch (__device__ globals; zero-init; self-resetting)
__device__ float g_partial[NB * NS * CCH];   // [b][s][c]
__device__ float g_gate[NB * CCH];
__device__ unsigned g_done[NB];              // per-batch pool counters
__device__ unsigned g_count = 0;             // barrier arrivals
__device__ unsigned g_gen   = 0;             // barrier generation

__device__ __forceinline__ void grid_barrier() {
    __syncthreads();
    if (threadIdx.x == 0) {
        unsigned gen = *((volatile unsigned*)&g_gen);
        __threadfence();
        if (atomicAdd(&g_count, 1u) == NBLK - 1) {
            g_count = 0;
            __threadfence();
            atomicAdd(&g_gen, 1u);
        } else {
            while (*((volatile unsigned*)&g_gen) == gen) { }
        }
        __threadfence();
    }
    __syncthreads();
}

struct SMem {
    float4 red[256];
    float  s_s[CCH];
    float  s_h[16];
    float  s_w1[CCH * 16];
    int    flag;
};

// Pool one 64-row unit v of half h; completing block runs batch MLP inline.
__device__ __forceinline__ void pool_unit(int h, int v, int t, int c4, int ho,
                                          const float4* __restrict__ x4,
                                          const float* __restrict__ w1,
                                          const float* __restrict__ b1,
                                          const float* __restrict__ w2,
                                          const float* __restrict__ b2,
                                          SMem* sm) {
    const int b = h * HB + v / NS, s = v - (v / NS) * NS;
    const size_t base = ((size_t)b * HW + (size_t)s * CHUNK + ho) * (CCH / 4) + c4;

    float4 acc = make_float4(0.f, 0.f, 0.f, 0.f);
#pragma unroll
    for (int k = 0; k < CHUNK; k += 4) {
        float4 vv = x4[base + (size_t)k * (CCH / 4)];
        acc.x += vv.x; acc.y += vv.y; acc.z += vv.z; acc.w += vv.w;
    }
    sm->red[t] = acc;
    __syncthreads();
    if (t < 64) {
        float4 a = sm->red[t], e = sm->red[t + 64], f = sm->red[t + 128], hh = sm->red[t + 192];
        float4 r = make_float4(a.x + e.x + f.x + hh.x,
                               a.y + e.y + f.y + hh.y,
                               a.z + e.z + f.z + hh.z,
                               a.w + e.w + f.w + hh.w);
        reinterpret_cast<float4*>(g_partial)[((size_t)b * NS + s) * (CCH / 4) + t] = r;
    }
    __syncthreads();
    if (t == 0) {
        __threadfence();                       // release partial stores (t0-only, post-bar)
        unsigned old = atomicAdd(&g_done[b], 1u);
        sm->flag = (old == NS - 1);
        if (sm->flag) __threadfence();         // acquire other blocks' partials
    }
    __syncthreads();
    if (!sm->flag) return;

    // ---- inline excitation MLP for batch b ----
    if (t == 0) g_done[b] = 0;                 // reset for next replay (sole accessor)
#pragma unroll
    for (int i = t; i < CCH * 16; i += 256) sm->s_w1[i] = w1[i];

    float accm = 0.f;
#pragma unroll 7
    for (int ss = 0; ss < NS; ss++)
        accm += __ldcg(&g_partial[((size_t)b * NS + ss) * CCH + t]);
    sm->s_s[t] = accm * (1.0f / (float)HW);
    __syncthreads();

    {   // dense1 parallelized: t = grp*16 + cout
        const int cout = t & 15;
        const int grp  = t >> 4;
        float p = 0.f;
#pragma unroll
        for (int k = grp * 16; k < grp * 16 + 16; k++)
            p = fmaf(sm->s_s[k], sm->s_w1[k * 16 + cout], p);
        reinterpret_cast<float*>(sm->red)[t] = p;
    }
    __syncthreads();
    if (t < 16) {
        float hd = b1[t];
#pragma unroll
        for (int j = 0; j < 16; j++)
            hd += reinterpret_cast<float*>(sm->red)[j * 16 + t];
        sm->s_h[t] = fmaxf(hd, 0.f);
    }
    __syncthreads();

    float g = b2[t];
#pragma unroll
    for (int j = 0; j < 16; j++)
        g = fmaf(sm->s_h[j], w2[j * CCH + t], g);
    g_gate[b * CCH + t] = 1.f / (1.f + __expf(-g));   // visibility via next grid_barrier
    __syncthreads();
}

__device__ __forceinline__ void scale_unit(int h, int v, int t, int c4, int ho,
                                           const float4* __restrict__ x4,
                                           float4* __restrict__ o4) {
    const int b = h * HB + v / NS, s = v - (v / NS) * NS;
    const float4 g = reinterpret_cast<const float4*>(g_gate)[b * (CCH / 4) + c4];
    const size_t base = ((size_t)b * HW + (size_t)s * CHUNK + ho) * (CCH / 4) + c4;
#pragma unroll
    for (int k = 0; k < CHUNK; k += 4) {
        const size_t idx = base + (size_t)k * (CCH / 4);
        float4 vv = x4[idx];                   // L2 hit (pooled last stage)
        vv.x *= g.x; vv.y *= g.y; vv.z *= g.z; vv.w *= g.w;
        o4[idx] = vv;                          // write-back: lazy drain (R11 win)
    }
}

__global__ void __launch_bounds__(256, 4)
k_se(const float* __restrict__ x,
     const float* __restrict__ w1,
     const float* __restrict__ b1,
     const float* __restrict__ w2,
     const float* __restrict__ b2,
     float* __restrict__ out) {
    const int bid = blockIdx.x;
    const int t   = threadIdx.x;
    const int c4  = t & 63;
    const int ho  = t >> 6;

    const float4* x4 = reinterpret_cast<const float4*>(x);
    float4*       o4 = reinterpret_cast<float4*>(out);

    __shared__ SMem sm;

    // ---- Stage A: all blocks pool half A (inline MLPs for batches 0..15) ----
    for (int v = bid; v < HUNITS; v += NBLK)
        pool_unit(0, v, t, c4, ho, x4, w1, b1, w2, b2, &sm);

    grid_barrier();   // gates(A) ready; x(A) hot in L2

    // ---- Stage B: role split — pool half B || scale half A (duplex streams) ----
    if (bid < HALFB) {
        for (int v = bid; v < HUNITS; v += HALFB)
            pool_unit(1, v, t, c4, ho, x4, w1, b1, w2, b2, &sm);
    } else {
        const int r = bid - HALFB;
        // reverse recency: stage A read v ascending, so high v = hottest
        for (int v = r + 2 * HALFB; v >= 0; v -= HALFB)
            if (v < HUNITS) scale_unit(0, v, t, c4, ho, x4, o4);
    }

    grid_barrier();   // gates(B) ready; x(B) hot in L2

    // ---- Stage C: all blocks scale half B (reverse recency) ----
    for (int v = bid + ((HUNITS - 1 - bid) / NBLK) * NBLK; v >= 0; v -= NBLK)
        scale_unit(1, v, t, c4, ho, x4, o4);
}

extern "C" void kernel_launch(void* const* d_in, const int* in_sizes, int n_in,
                              void* d_out, int out_size) {
    const float* x  = (const float*)d_in[0];
    const float* w1 = (const float*)d_in[1];
    const float* b1 = (const float*)d_in[2];
    const float* w2 = (const float*)d_in[3];
    const float* b2 = (const float*)d_in[4];
    float* out = (float*)d_out;

    k_se<<<NBLK, 256>>>(x, w1, b1, w2, b2, out);
}